// round 15
// baseline (speedup 1.0000x reference)
#include <cuda_runtime.h>
#include <cuda_bf16.h>

// ManagerStateTracker: B=1024, P=64, N=512, E=256, F=64
// out row (width 12800):
//   [0,64) feas  [64,192) work  [192,4288) known  [4288,8384) unknown
//   [8384,12480) differ  [12480,12544) qa
//   [12544,12800) agg_state = mean_p tanh(embed[b, nodes[b,p], :] @ W + b)

#define BDIM 1024
#define PDIM 64
#define NDIM 512
#define EDIM 256
#define OUTW 12800
#define COPYW 12544

#define XPAD 264   // X smem pitch (bf16): 528B = 33*16B -> conflict-free ldmatrix

#define XS_BYTES    (PDIM * XPAD * 2)       // 33792
#define STAGE_BYTES (PDIM * EDIM * 4)       // 65536 fp32 gather stage
#define MBAR_OFF    (XS_BYTES + STAGE_BYTES)
#define SMEM_TOTAL  (MBAR_OFF + 16)         // 99344 -> 2 CTAs/SM

// W pre-packed into mma B-fragment order:
// g_Wfrag[w(8)][kstep(16)][nt(4)][lane(32)] = uint2{b0, b1}
__device__ uint2 g_Wfrag[8 * 16 * 4 * 32];   // 128KB, L1-resident per SM

__device__ __forceinline__ float tanh_fast(float x) {
    asm("tanh.approx.f32 %0, %0;" : "+f"(x)); return x;
}

__device__ __forceinline__ void mma_bf16(float& d0, float& d1, float& d2, float& d3,
                                         unsigned a0, unsigned a1, unsigned a2, unsigned a3,
                                         unsigned b0, unsigned b1) {
    asm("mma.sync.aligned.m16n8k16.row.col.f32.bf16.bf16.f32 "
        "{%0,%1,%2,%3}, {%4,%5,%6,%7}, {%8,%9}, {%0,%1,%2,%3};"
        : "+f"(d0), "+f"(d1), "+f"(d2), "+f"(d3)
        : "r"(a0), "r"(a1), "r"(a2), "r"(a3), "r"(b0), "r"(b1));
}

__device__ __forceinline__ void ldsm_x4(unsigned& r0, unsigned& r1,
                                        unsigned& r2, unsigned& r3, const void* p) {
    unsigned addr = (unsigned)__cvta_generic_to_shared(p);
    asm volatile("ldmatrix.sync.aligned.m8n8.x4.shared.b16 {%0,%1,%2,%3}, [%4];"
                 : "=r"(r0), "=r"(r1), "=r"(r2), "=r"(r3) : "r"(addr));
}

__device__ __forceinline__ void bulk_g2s(void* sdst, const void* gsrc,
                                         unsigned bytes, unsigned mbar) {
    unsigned d = (unsigned)__cvta_generic_to_shared(sdst);
    asm volatile(
        "cp.async.bulk.shared::cta.global.mbarrier::complete_tx::bytes "
        "[%0], [%1], %2, [%3];"
        :: "r"(d), "l"(gsrc), "r"(bytes), "r"(mbar) : "memory");
}

__device__ __forceinline__ void mbar_wait(unsigned mbar, unsigned parity) {
    asm volatile(
        "{\n\t.reg .pred p;\n\t"
        "WAITLP%=:\n\t"
        "mbarrier.try_wait.parity.shared.b64 p, [%0], %1, 0x989680;\n\t"
        "@p bra WAITDN%=;\n\t"
        "bra WAITLP%=;\n\t"
        "WAITDN%=:\n\t}"
        :: "r"(mbar), "r"(parity) : "memory");
}

// ---------------------------------------------------------------------------
// Kernel 0: W (E,E) fp32 [k][n] -> fragment-packed bf16 g_Wfrag
// ---------------------------------------------------------------------------
__global__ void wconv_kernel(const float* __restrict__ W) {
    int idx = blockIdx.x * blockDim.x + threadIdx.x;   // 16384 slots
    int lane = idx & 31;
    int nt   = (idx >> 5) & 3;
    int ks   = (idx >> 7) & 15;
    int w    = idx >> 11;
    int g  = lane >> 2;
    int t4 = lane & 3;
    int n  = w * 32 + nt * 8 + g;
    int k0 = ks * 16 + 2 * t4;
    __nv_bfloat162 lo = __floats2bfloat162_rn(W[(k0)     * EDIM + n],
                                              W[(k0 + 1) * EDIM + n]);
    __nv_bfloat162 hi = __floats2bfloat162_rn(W[(k0 + 8) * EDIM + n],
                                              W[(k0 + 9) * EDIM + n]);
    g_Wfrag[idx] = make_uint2(*reinterpret_cast<unsigned*>(&lo),
                              *reinterpret_cast<unsigned*>(&hi));
}

// ---------------------------------------------------------------------------
// Kernel 1: 2 batches/CTA, software-pipelined.
// Gather runs on the TMA engine (64 x 1KB bulk G->S per batch) into an fp32
// stage; batch i+1's gather streams DURING batch i's MMA. Concat copy stays
// thread-side (R13 interleave). 256 threads, warp w: n-slice [32w,32w+32).
// smem: Xs 33KB + stage 64KB + mbar = 97.5KB -> 2 CTAs/SM.
// ---------------------------------------------------------------------------
__global__ void __launch_bounds__(256, 2)
fused_kernel(const float* __restrict__ feas,
             const float* __restrict__ work,
             const float* __restrict__ known,
             const float* __restrict__ unknown,
             const float* __restrict__ differ,
             const float* __restrict__ qa,
             const int*   __restrict__ nodes32,   // int32 OR int64 (probed)
             const float* __restrict__ embed,     // (B, N, E)
             const float* __restrict__ bias,      // (E,)
             float* __restrict__ out) {
    extern __shared__ char smraw[];
    __nv_bfloat16* Xs = reinterpret_cast<__nv_bfloat16*>(smraw);      // [64][XPAD]
    float* stg = reinterpret_cast<float*>(smraw + XS_BYTES);          // [64][256]
    const unsigned mbar = (unsigned)__cvta_generic_to_shared(smraw + MBAR_OFF);

    const int t    = threadIdx.x;
    const int lane = t & 31;
    const int warp = t >> 5;
    const int base = 2 * blockIdx.x;

    // ---- int64 probe, per-warp, barrier-free.
    // If dtype is int64 (values < 512) all 32 high words are 0.
    // P(false positive for random int32 in [0,512)) = (1/512)^32 ~ 0.
    const bool is64 =
        (__ballot_sync(0xffffffffu, nodes32[2 * lane + 1] != 0) == 0u);

    if (t == 0)
        asm volatile("mbarrier.init.shared.b64 [%0], %1;" :: "r"(mbar), "r"(1));
    __syncthreads();

    // ---- Issue TMA gather for batch 0 (warp 0; 2 rows per lane).
    if (warp == 0) {
        const int gi0 = base * PDIM;
        int n0 = is64 ? nodes32[2 * (gi0 + lane)]      : nodes32[gi0 + lane];
        int n1 = is64 ? nodes32[2 * (gi0 + lane + 32)] : nodes32[gi0 + lane + 32];
        if (lane == 0)
            asm volatile("mbarrier.arrive.expect_tx.shared.b64 _, [%0], %1;"
                         :: "r"(mbar), "r"((unsigned)STAGE_BYTES));
        __syncwarp();
        bulk_g2s(stg + lane * EDIM,
                 embed + ((size_t)base * NDIM + n0) * EDIM, 1024, mbar);
        bulk_g2s(stg + (lane + 32) * EDIM,
                 embed + ((size_t)base * NDIM + n1) * EDIM, 1024, mbar);
    }

    const int g    = lane >> 2;
    const int t4   = lane & 3;
    const int nb   = warp * 32;
    const int lrow = lane & 15;
    const int lcol = (lane >> 4) * 8;

    for (int ib = 0; ib < 2; ib++) {
        const int b = base + ib;
        float* orow = out + (size_t)b * OUTW;
        const float* bsrc[3] = { known   + b * 4096,
                                 unknown + b * 4096,
                                 differ  + b * 4096 };

        // ---- Copy first half + small blocks (fills gather/drain window).
        {
            float4 v[6];
            #pragma unroll
            for (int j = 0; j < 6; j++) {
                int idx = t + j * 256;
                v[j] = reinterpret_cast<const float4*>(bsrc[idx >> 10])[idx & 1023];
            }
            #pragma unroll
            for (int j = 0; j < 6; j++) {
                int idx = t + j * 256;
                reinterpret_cast<float4*>(orow + 192 + (idx >> 10) * 4096)[idx & 1023] = v[j];
            }
            if (t < 64) {
                const float* src;
                int c;
                if (t < 16)      { src = feas + b * 64  + 4 * t;        c = 4 * t; }
                else if (t < 48) { src = work + b * 128 + 4 * (t - 16); c = 64 + 4 * (t - 16); }
                else             { src = qa   + b * 64  + 4 * (t - 48); c = 12480 + 4 * (t - 48); }
                *reinterpret_cast<float4*>(orow + c) =
                    *reinterpret_cast<const float4*>(src);
            }
        }

        // ---- Wait gather(b), convert stage fp32 -> Xs bf16.
        mbar_wait(mbar, (unsigned)ib);
        __syncthreads();   // also: prior MMA readers done before Xs overwrite
        {
            const int c0 = (t & 63) * 4;
            const int rb = (t >> 6) * 16;
            #pragma unroll
            for (int r = 0; r < 16; r++) {
                float4 v = *reinterpret_cast<const float4*>(stg + (rb + r) * EDIM + c0);
                __nv_bfloat162 lo = __floats2bfloat162_rn(v.x, v.y);
                __nv_bfloat162 hi = __floats2bfloat162_rn(v.z, v.w);
                reinterpret_cast<uint2*>(Xs + (rb + r) * XPAD + c0)[0] =
                    make_uint2(*reinterpret_cast<unsigned*>(&lo),
                               *reinterpret_cast<unsigned*>(&hi));
            }
        }
        __syncthreads();   // Xs ready, stage free

        // ---- Issue TMA gather for batch 1 (overlaps MMA(b0)).
        if (ib == 0 && warp == 0) {
            const int gi0 = (base + 1) * PDIM;
            int n0 = is64 ? nodes32[2 * (gi0 + lane)]      : nodes32[gi0 + lane];
            int n1 = is64 ? nodes32[2 * (gi0 + lane + 32)] : nodes32[gi0 + lane + 32];
            if (lane == 0)
                asm volatile("mbarrier.arrive.expect_tx.shared.b64 _, [%0], %1;"
                             :: "r"(mbar), "r"((unsigned)STAGE_BYTES));
            __syncwarp();
            bulk_g2s(stg + lane * EDIM,
                     embed + ((size_t)(base + 1) * NDIM + n0) * EDIM, 1024, mbar);
            bulk_g2s(stg + (lane + 32) * EDIM,
                     embed + ((size_t)(base + 1) * NDIM + n1) * EDIM, 1024, mbar);
        }

        // ---- MMA with second copy-half interleaved (lag-5 rotation).
        float acc[4][4][4];
        #pragma unroll
        for (int mt = 0; mt < 4; mt++)
            #pragma unroll
            for (int nt = 0; nt < 4; nt++)
                #pragma unroll
                for (int j = 0; j < 4; j++) acc[mt][nt][j] = 0.0f;

        const uint2* wf_base = g_Wfrag + warp * (16 * 4 * 32) + lane;
        float4 cl[3];

        #pragma unroll
        for (int ks = 0; ks < 16; ks++) {
            const int k0 = ks * 16;
            uint2 bf[4];
            #pragma unroll
            for (int nt = 0; nt < 4; nt++)
                bf[nt] = __ldg(wf_base + (ks * 4 + nt) * 32);

            if ((ks & 1) == 0 && ks <= 10) {
                int j = 6 + (ks >> 1);
                int idx = t + j * 256;
                cl[(ks >> 1) % 3] =
                    reinterpret_cast<const float4*>(bsrc[idx >> 10])[idx & 1023];
            }

            #pragma unroll
            for (int mt = 0; mt < 4; mt++) {
                unsigned a0, a1, a2, a3;
                ldsm_x4(a0, a1, a2, a3, Xs + (mt * 16 + lrow) * XPAD + k0 + lcol);
                #pragma unroll
                for (int nt = 0; nt < 4; nt++)
                    mma_bf16(acc[mt][nt][0], acc[mt][nt][1],
                             acc[mt][nt][2], acc[mt][nt][3],
                             a0, a1, a2, a3, bf[nt].x, bf[nt].y);
            }

            if ((ks & 1) == 1 && ks >= 5) {
                int j = 6 + ((ks - 5) >> 1);
                int idx = t + j * 256;
                reinterpret_cast<float4*>(orow + 192 + (idx >> 10) * 4096)[idx & 1023] =
                    cl[((ks - 5) >> 1) % 3];
            }
        }

        // ---- Epilogue: tanh(.+bias), sum over M, shfl-reduce over g.
        float s0[4], s1[4];
        #pragma unroll
        for (int nt = 0; nt < 4; nt++) {
            const int c = nb + nt * 8 + 2 * t4;
            const float bz0 = __ldg(bias + c);
            const float bz1 = __ldg(bias + c + 1);
            float a = 0.f, bsum = 0.f;
            #pragma unroll
            for (int mt = 0; mt < 4; mt++) {
                a    += tanh_fast(acc[mt][nt][0] + bz0) + tanh_fast(acc[mt][nt][2] + bz0);
                bsum += tanh_fast(acc[mt][nt][1] + bz1) + tanh_fast(acc[mt][nt][3] + bz1);
            }
            s0[nt] = a; s1[nt] = bsum;
        }
        #pragma unroll
        for (int off = 4; off <= 16; off <<= 1) {
            #pragma unroll
            for (int nt = 0; nt < 4; nt++) {
                s0[nt] += __shfl_xor_sync(0xffffffffu, s0[nt], off);
                s1[nt] += __shfl_xor_sync(0xffffffffu, s1[nt], off);
            }
        }
        if (g == 0) {
            float* arow = orow + COPYW;
            #pragma unroll
            for (int nt = 0; nt < 4; nt++) {
                const int c = nb + nt * 8 + 2 * t4;
                arow[c]     = s0[nt] * (1.0f / (float)PDIM);
                arow[c + 1] = s1[nt] * (1.0f / (float)PDIM);
            }
        }
    }
}

// ---------------------------------------------------------------------------
extern "C" void kernel_launch(void* const* d_in, const int* in_sizes, int n_in,
                              void* d_out, int out_size) {
    const float* feas    = (const float*)d_in[0];
    const float* work    = (const float*)d_in[1];
    const float* known   = (const float*)d_in[2];
    const float* unknown = (const float*)d_in[3];
    const float* differ  = (const float*)d_in[4];
    const float* qa      = (const float*)d_in[5];
    const int*   nodes   = (const int*)d_in[6];
    const float* embed   = (const float*)d_in[7];
    const float* W       = (const float*)d_in[8];
    const float* bias    = (const float*)d_in[9];
    float* out = (float*)d_out;

    static bool attr_set = false;
    if (!attr_set) {
        cudaFuncSetAttribute(fused_kernel,
                             cudaFuncAttributeMaxDynamicSharedMemorySize, SMEM_TOTAL);
        attr_set = true;
    }

    wconv_kernel<<<64, 256>>>(W);
    fused_kernel<<<BDIM / 2, 256, SMEM_TOTAL>>>(
        feas, work, known, unknown, differ, qa, nodes, embed, bias, out);
}

// round 17
// speedup vs baseline: 1.0831x; 1.0831x over previous
#include <cuda_runtime.h>
#include <cuda_bf16.h>

// ManagerStateTracker: B=1024, P=64, N=512, E=256, F=64
// out row (width 12800):
//   [0,64) feas  [64,192) work  [192,4288) known  [4288,8384) unknown
//   [8384,12480) differ  [12480,12544) qa
//   [12544,12800) agg_state = mean_p tanh(embed[b, nodes[b,p], :] @ W + b)

#define BDIM 1024
#define PDIM 64
#define NDIM 512
#define EDIM 256
#define OUTW 12800
#define COPYW 12544

#define XPAD 264   // X smem pitch (bf16): 528B = 33*16B -> conflict-free ldmatrix
#define XS_BYTES (PDIM * XPAD * 2)           // 33792 per buffer
#define SMEM_TOTAL (2 * XS_BYTES)            // 67584 -> 2 CTAs/SM

// W pre-packed into mma B-fragment order:
// g_Wfrag[w(8)][kstep(16)][nt(4)][lane(32)] = uint2{b0, b1}
__device__ uint2 g_Wfrag[8 * 16 * 4 * 32];   // 128KB, L1-resident per SM

__device__ __forceinline__ float tanh_fast(float x) {
    asm("tanh.approx.f32 %0, %0;" : "+f"(x)); return x;
}

__device__ __forceinline__ void mma_bf16(float& d0, float& d1, float& d2, float& d3,
                                         unsigned a0, unsigned a1, unsigned a2, unsigned a3,
                                         unsigned b0, unsigned b1) {
    asm("mma.sync.aligned.m16n8k16.row.col.f32.bf16.bf16.f32 "
        "{%0,%1,%2,%3}, {%4,%5,%6,%7}, {%8,%9}, {%0,%1,%2,%3};"
        : "+f"(d0), "+f"(d1), "+f"(d2), "+f"(d3)
        : "r"(a0), "r"(a1), "r"(a2), "r"(a3), "r"(b0), "r"(b1));
}

__device__ __forceinline__ void ldsm_x4(unsigned& r0, unsigned& r1,
                                        unsigned& r2, unsigned& r3, const void* p) {
    unsigned addr = (unsigned)__cvta_generic_to_shared(p);
    asm volatile("ldmatrix.sync.aligned.m8n8.x4.shared.b16 {%0,%1,%2,%3}, [%4];"
                 : "=r"(r0), "=r"(r1), "=r"(r2), "=r"(r3) : "r"(addr));
}

// Convert one gathered float4 and store as 8B into Xs row.
__device__ __forceinline__ void cvt_sts(__nv_bfloat16* drow, int lane, int half,
                                        const float4& v) {
    __nv_bfloat162 lo = __floats2bfloat162_rn(v.x, v.y);
    __nv_bfloat162 hi = __floats2bfloat162_rn(v.z, v.w);
    reinterpret_cast<uint2*>(drow + half * 128 + lane * 4)[0] =
        make_uint2(*reinterpret_cast<unsigned*>(&lo),
                   *reinterpret_cast<unsigned*>(&hi));
}

// ---------------------------------------------------------------------------
// Kernel 0: W (E,E) fp32 [k][n] -> fragment-packed bf16 g_Wfrag
// ---------------------------------------------------------------------------
__global__ void wconv_kernel(const float* __restrict__ W) {
    int idx = blockIdx.x * blockDim.x + threadIdx.x;   // 16384 slots
    int lane = idx & 31;
    int nt   = (idx >> 5) & 3;
    int ks   = (idx >> 7) & 15;
    int w    = idx >> 11;
    int g  = lane >> 2;
    int t4 = lane & 3;
    int n  = w * 32 + nt * 8 + g;
    int k0 = ks * 16 + 2 * t4;
    __nv_bfloat162 lo = __floats2bfloat162_rn(W[(k0)     * EDIM + n],
                                              W[(k0 + 1) * EDIM + n]);
    __nv_bfloat162 hi = __floats2bfloat162_rn(W[(k0 + 8) * EDIM + n],
                                              W[(k0 + 9) * EDIM + n]);
    g_Wfrag[idx] = make_uint2(*reinterpret_cast<unsigned*>(&lo),
                              *reinterpret_cast<unsigned*>(&hi));
}

// ---------------------------------------------------------------------------
// Kernel 1: 2 batches/CTA, double-buffered Xs.
//   b0: direct gather -> XsA; barrier; MMA(b0) with [b1-gather -> XsB] and
//   [b0 copy 2nd half] interleaved into the 16-step loop; epilogue(b0);
//   b1 copy 1st half; barrier; MMA(b1) with [b1 copy 2nd half]; epilogue(b1).
// Gather rotation: store for step ks-4 happens BEFORE the load of step ks
// (same gv slot, depth 4 = lag 4 -> store-first is required for correctness).
// 256 threads (8 warps), warp w: n-slice [32w, 32w+32).
// ---------------------------------------------------------------------------
__global__ void __launch_bounds__(256, 2)
fused_kernel(const float* __restrict__ feas,
             const float* __restrict__ work,
             const float* __restrict__ known,
             const float* __restrict__ unknown,
             const float* __restrict__ differ,
             const float* __restrict__ qa,
             const int*   __restrict__ nodes32,   // int32 OR int64 (probed)
             const float* __restrict__ embed,     // (B, N, E)
             const float* __restrict__ bias,      // (E,)
             float* __restrict__ out) {
    extern __shared__ char smraw[];
    __nv_bfloat16* XsA = reinterpret_cast<__nv_bfloat16*>(smraw);
    __nv_bfloat16* XsB = reinterpret_cast<__nv_bfloat16*>(smraw + XS_BYTES);

    const int t    = threadIdx.x;
    const int lane = t & 31;
    const int warp = t >> 5;
    const int b0   = 2 * blockIdx.x;
    const int b1   = b0 + 1;

    // ---- int64 probe, per-warp, barrier-free.
    // If dtype is int64 (values < 512) all 32 high words are 0.
    // P(false positive for random int32 in [0,512)) = (1/512)^32 ~ 0.
    const bool is64 =
        (__ballot_sync(0xffffffffu, nodes32[2 * lane + 1] != 0) == 0u);

    const int g    = lane >> 2;
    const int t4   = lane & 3;
    const int nb   = warp * 32;
    const int lrow = lane & 15;
    const int lcol = (lane >> 4) * 8;
    const uint2* wf_base = g_Wfrag + warp * (16 * 4 * 32) + lane;

    float* orow0 = out + (size_t)b0 * OUTW;
    float* orow1 = out + (size_t)b1 * OUTW;
    const float* bsrc0[3] = { known + b0 * 4096, unknown + b0 * 4096, differ + b0 * 4096 };
    const float* bsrc1[3] = { known + b1 * 4096, unknown + b1 * 4096, differ + b1 * 4096 };

    // ---- Phase 1: direct gather b0 -> XsA (rows 8w..8w+7, nL=4 LDG.128).
    {
        const int gi0 = b0 * PDIM + warp * 8;
        int myn = 0;
        if (lane < 8)
            myn = is64 ? nodes32[2 * (gi0 + lane)] : nodes32[gi0 + lane];
        #pragma unroll
        for (int r = 0; r < 8; r++) {
            const int node = __shfl_sync(0xffffffffu, myn, r);
            const float4* src =
                reinterpret_cast<const float4*>(embed + ((size_t)b0 * NDIM + node) * EDIM);
            float4 v0 = src[lane];
            float4 v1 = src[lane + 32];
            __nv_bfloat16* drow = XsA + (warp * 8 + r) * XPAD;
            cvt_sts(drow, lane, 0, v0);
            cvt_sts(drow, lane, 1, v1);
        }
    }

    // ---- b0 copy first half + small blocks.
    {
        float4 v[6];
        #pragma unroll
        for (int j = 0; j < 6; j++) {
            int idx = t + j * 256;
            v[j] = reinterpret_cast<const float4*>(bsrc0[idx >> 10])[idx & 1023];
        }
        #pragma unroll
        for (int j = 0; j < 6; j++) {
            int idx = t + j * 256;
            reinterpret_cast<float4*>(orow0 + 192 + (idx >> 10) * 4096)[idx & 1023] = v[j];
        }
        if (t < 64) {
            const float* src;
            int c;
            if (t < 16)      { src = feas + b0 * 64  + 4 * t;        c = 4 * t; }
            else if (t < 48) { src = work + b0 * 128 + 4 * (t - 16); c = 64 + 4 * (t - 16); }
            else             { src = qa   + b0 * 64  + 4 * (t - 48); c = 12480 + 4 * (t - 48); }
            *reinterpret_cast<float4*>(orow0 + c) = *reinterpret_cast<const float4*>(src);
        }
    }

    // b1 node indices for the interleaved gather (8 per warp, in lane<8).
    int myn1 = 0;
    {
        const int gi1 = b1 * PDIM + warp * 8;
        if (lane < 8)
            myn1 = is64 ? nodes32[2 * (gi1 + lane)] : nodes32[gi1 + lane];
    }
    __syncthreads();   // XsA ready

    // ---- Phase 2: MMA(b0) with b1-gather and b0-copy interleaved.
    float acc[4][4][4];
    #pragma unroll
    for (int mt = 0; mt < 4; mt++)
        #pragma unroll
        for (int nt = 0; nt < 4; nt++)
            #pragma unroll
            for (int j = 0; j < 4; j++) acc[mt][nt][j] = 0.0f;

    float4 cl[3];      // copy in-flight
    float4 gv[4];      // gather in-flight (depth 4, lag 4; store-first)

    #pragma unroll
    for (int ks = 0; ks < 16; ks++) {
        const int k0 = ks * 16;
        uint2 bf[4];
        #pragma unroll
        for (int nt = 0; nt < 4; nt++)
            bf[nt] = __ldg(wf_base + (ks * 4 + nt) * 32);

        // gather STORE first (step s2 = ks-4; reads slot loaded 4 iters ago,
        // which the load below will overwrite)
        if (ks >= 4) {
            const int s2 = ks - 4;
            cvt_sts(XsB + (warp * 8 + (s2 >> 1)) * XPAD, lane, s2 & 1, gv[s2 & 3]);
        }
        // gather LOAD: step ks -> row (ks>>1), half (ks&1)
        {
            const int node = __shfl_sync(0xffffffffu, myn1, ks >> 1);
            const float4* src =
                reinterpret_cast<const float4*>(embed + ((size_t)b1 * NDIM + node) * EDIM);
            gv[ks & 3] = src[(ks & 1) * 32 + lane];
        }
        // copy load: even ks <= 10
        if ((ks & 1) == 0 && ks <= 10) {
            int idx = t + (6 + (ks >> 1)) * 256;
            cl[(ks >> 1) % 3] =
                reinterpret_cast<const float4*>(bsrc0[idx >> 10])[idx & 1023];
        }

        #pragma unroll
        for (int mt = 0; mt < 4; mt++) {
            unsigned a0, a1, a2, a3;
            ldsm_x4(a0, a1, a2, a3, XsA + (mt * 16 + lrow) * XPAD + k0 + lcol);
            #pragma unroll
            for (int nt = 0; nt < 4; nt++)
                mma_bf16(acc[mt][nt][0], acc[mt][nt][1],
                         acc[mt][nt][2], acc[mt][nt][3],
                         a0, a1, a2, a3, bf[nt].x, bf[nt].y);
        }

        // copy store: odd ks >= 5
        if ((ks & 1) == 1 && ks >= 5) {
            int idx = t + (6 + ((ks - 5) >> 1)) * 256;
            reinterpret_cast<float4*>(orow0 + 192 + (idx >> 10) * 4096)[idx & 1023] =
                cl[((ks - 5) >> 1) % 3];
        }
    }
    // drain last 4 gather stores (values loaded at ks = 12..15)
    #pragma unroll
    for (int s2 = 12; s2 < 16; s2++)
        cvt_sts(XsB + (warp * 8 + (s2 >> 1)) * XPAD, lane, s2 & 1, gv[s2 & 3]);

    // ---- Epilogue b0.
    {
        float s0[4], s1[4];
        #pragma unroll
        for (int nt = 0; nt < 4; nt++) {
            const int c = nb + nt * 8 + 2 * t4;
            const float bz0 = __ldg(bias + c);
            const float bz1 = __ldg(bias + c + 1);
            float a = 0.f, bs = 0.f;
            #pragma unroll
            for (int mt = 0; mt < 4; mt++) {
                a  += tanh_fast(acc[mt][nt][0] + bz0) + tanh_fast(acc[mt][nt][2] + bz0);
                bs += tanh_fast(acc[mt][nt][1] + bz1) + tanh_fast(acc[mt][nt][3] + bz1);
            }
            s0[nt] = a; s1[nt] = bs;
        }
        #pragma unroll
        for (int off = 4; off <= 16; off <<= 1)
            #pragma unroll
            for (int nt = 0; nt < 4; nt++) {
                s0[nt] += __shfl_xor_sync(0xffffffffu, s0[nt], off);
                s1[nt] += __shfl_xor_sync(0xffffffffu, s1[nt], off);
            }
        if (g == 0) {
            float* arow = orow0 + COPYW;
            #pragma unroll
            for (int nt = 0; nt < 4; nt++) {
                const int c = nb + nt * 8 + 2 * t4;
                arow[c]     = s0[nt] * (1.0f / (float)PDIM);
                arow[c + 1] = s1[nt] * (1.0f / (float)PDIM);
            }
        }
    }

    // ---- b1 copy first half + small blocks (fills barrier window).
    {
        float4 v[6];
        #pragma unroll
        for (int j = 0; j < 6; j++) {
            int idx = t + j * 256;
            v[j] = reinterpret_cast<const float4*>(bsrc1[idx >> 10])[idx & 1023];
        }
        #pragma unroll
        for (int j = 0; j < 6; j++) {
            int idx = t + j * 256;
            reinterpret_cast<float4*>(orow1 + 192 + (idx >> 10) * 4096)[idx & 1023] = v[j];
        }
        if (t < 64) {
            const float* src;
            int c;
            if (t < 16)      { src = feas + b1 * 64  + 4 * t;        c = 4 * t; }
            else if (t < 48) { src = work + b1 * 128 + 4 * (t - 16); c = 64 + 4 * (t - 16); }
            else             { src = qa   + b1 * 64  + 4 * (t - 48); c = 12480 + 4 * (t - 48); }
            *reinterpret_cast<float4*>(orow1 + c) = *reinterpret_cast<const float4*>(src);
        }
    }
    __syncthreads();   // XsB ready

    // ---- Phase 3: MMA(b1) with b1-copy interleaved.
    #pragma unroll
    for (int mt = 0; mt < 4; mt++)
        #pragma unroll
        for (int nt = 0; nt < 4; nt++)
            #pragma unroll
            for (int j = 0; j < 4; j++) acc[mt][nt][j] = 0.0f;

    #pragma unroll
    for (int ks = 0; ks < 16; ks++) {
        const int k0 = ks * 16;
        uint2 bf[4];
        #pragma unroll
        for (int nt = 0; nt < 4; nt++)
            bf[nt] = __ldg(wf_base + (ks * 4 + nt) * 32);

        if ((ks & 1) == 0 && ks <= 10) {
            int idx = t + (6 + (ks >> 1)) * 256;
            cl[(ks >> 1) % 3] =
                reinterpret_cast<const float4*>(bsrc1[idx >> 10])[idx & 1023];
        }

        #pragma unroll
        for (int mt = 0; mt < 4; mt++) {
            unsigned a0, a1, a2, a3;
            ldsm_x4(a0, a1, a2, a3, XsB + (mt * 16 + lrow) * XPAD + k0 + lcol);
            #pragma unroll
            for (int nt = 0; nt < 4; nt++)
                mma_bf16(acc[mt][nt][0], acc[mt][nt][1],
                         acc[mt][nt][2], acc[mt][nt][3],
                         a0, a1, a2, a3, bf[nt].x, bf[nt].y);
        }

        if ((ks & 1) == 1 && ks >= 5) {
            int idx = t + (6 + ((ks - 5) >> 1)) * 256;
            reinterpret_cast<float4*>(orow1 + 192 + (idx >> 10) * 4096)[idx & 1023] =
                cl[((ks - 5) >> 1) % 3];
        }
    }

    // ---- Epilogue b1.
    {
        float s0[4], s1[4];
        #pragma unroll
        for (int nt = 0; nt < 4; nt++) {
            const int c = nb + nt * 8 + 2 * t4;
            const float bz0 = __ldg(bias + c);
            const float bz1 = __ldg(bias + c + 1);
            float a = 0.f, bs = 0.f;
            #pragma unroll
            for (int mt = 0; mt < 4; mt++) {
                a  += tanh_fast(acc[mt][nt][0] + bz0) + tanh_fast(acc[mt][nt][2] + bz0);
                bs += tanh_fast(acc[mt][nt][1] + bz1) + tanh_fast(acc[mt][nt][3] + bz1);
            }
            s0[nt] = a; s1[nt] = bs;
        }
        #pragma unroll
        for (int off = 4; off <= 16; off <<= 1)
            #pragma unroll
            for (int nt = 0; nt < 4; nt++) {
                s0[nt] += __shfl_xor_sync(0xffffffffu, s0[nt], off);
                s1[nt] += __shfl_xor_sync(0xffffffffu, s1[nt], off);
            }
        if (g == 0) {
            float* arow = orow1 + COPYW;
            #pragma unroll
            for (int nt = 0; nt < 4; nt++) {
                const int c = nb + nt * 8 + 2 * t4;
                arow[c]     = s0[nt] * (1.0f / (float)PDIM);
                arow[c + 1] = s1[nt] * (1.0f / (float)PDIM);
            }
        }
    }
}

// ---------------------------------------------------------------------------
extern "C" void kernel_launch(void* const* d_in, const int* in_sizes, int n_in,
                              void* d_out, int out_size) {
    const float* feas    = (const float*)d_in[0];
    const float* work    = (const float*)d_in[1];
    const float* known   = (const float*)d_in[2];
    const float* unknown = (const float*)d_in[3];
    const float* differ  = (const float*)d_in[4];
    const float* qa      = (const float*)d_in[5];
    const int*   nodes   = (const int*)d_in[6];
    const float* embed   = (const float*)d_in[7];
    const float* W       = (const float*)d_in[8];
    const float* bias    = (const float*)d_in[9];
    float* out = (float*)d_out;

    static bool attr_set = false;
    if (!attr_set) {
        cudaFuncSetAttribute(fused_kernel,
                             cudaFuncAttributeMaxDynamicSharedMemorySize, SMEM_TOTAL);
        attr_set = true;
    }

    wconv_kernel<<<64, 256>>>(W);
    fused_kernel<<<BDIM / 2, 256, SMEM_TOTAL>>>(
        feas, work, known, unknown, differ, qa, nodes, embed, bias, out);
}